// round 13
// baseline (speedup 1.0000x reference)
#include <cuda_runtime.h>
#include <cuda_bf16.h>
#include <cuda_fp16.h>
#include <mma.h>
#include <cstdint>
#include <math.h>

using namespace nvcuda;

#define F 256
#define MAXN 100000
#define MAXE 3200000
#define ELLW 128

// ---------------- device scratch ----------------
__device__ __half g_H16[(size_t)MAXN * F];      // SpMM1 output (fp16, read by GEMM2)
__device__ __half g_Xh[(size_t)MAXN * F];       // fp16 copy of current GEMM output
__device__ int   g_cnt[MAXN];                   // per-row edge count (ELL)
__device__ uint2 g_edge[(size_t)MAXN * ELLW];   // ELL: packed (col, val_bits)
__device__ float g_stats[2 * F];                // [0:256) sum, [256:512) sumsq
__device__ __half g_Wh[2 * F * F];              // W1, W2 pre-converted to fp16

__device__ __forceinline__ uint32_t smem_u32(const void* p) {
    uint32_t a;
    asm("{ .reg .u64 t; cvta.to.shared.u64 t, %1; cvt.u32.u64 %0, t; }" : "=r"(a) : "l"(p));
    return a;
}

// ---------------- ELL build (single kernel; cnt pre-zeroed by memset) ----------------
__global__ void k_ell(const int* __restrict__ rows, const int* __restrict__ cols,
                      const float* __restrict__ vals, int E) {
    int e = blockIdx.x * blockDim.x + threadIdx.x;
    if (e < E) {
        int r = __ldcs(rows + e);
        int pos = atomicAdd(&g_cnt[r], 1);
        g_edge[(size_t)r * ELLW + pos] = make_uint2((uint32_t)__ldcs(cols + e),
                                                    __float_as_uint(__ldcs(vals + e)));
    }
}

// ---------------- W convert to fp16 (+ zero stats) ----------------
__global__ void k_prep_w(const float* __restrict__ W1, const float* __restrict__ W2) {
    int i = blockIdx.x * blockDim.x + threadIdx.x;
    if (blockIdx.x == 0) { g_stats[threadIdx.x] = 0.f; g_stats[threadIdx.x + 256] = 0.f; }
    g_Wh[i]         = __float2half_rn(W1[i]);
    g_Wh[i + F * F] = __float2half_rn(W2[i]);
}

// ---------------- fp16 wmma GEMM (A: fp32 or fp16), fp16 output ----------------
#define ALD_H 40
#define BLD_H 264
#define ASZ_H (64 * ALD_H)
#define BSZ_H (32 * BLD_H)
#define STAGE_H (ASZ_H + BSZ_H)
#define EPLD 264

__device__ __forceinline__ void cp16(uint32_t dst, const void* src) {
    asm volatile("cp.async.ca.shared.global [%0], [%1], 16;" :: "r"(dst), "l"(src));
}

template <int AHALF, int BNRELU>
__global__ void __launch_bounds__(256)
k_gemm_wmma(const void* __restrict__ Av, const __half* __restrict__ Wh,
            __half* __restrict__ Ch, int M,
            const float* __restrict__ gamma, const float* __restrict__ beta) {
    extern __shared__ float sm[];
    __half* smh = reinterpret_cast<__half*>(sm);
    __shared__ float sa[256], sb[256];
    int tid = threadIdx.x;
    int wid = tid >> 5;
    int warp_row = wid >> 2;
    int warp_col = wid & 3;
    int row0 = blockIdx.x * 64;

    if constexpr (BNRELU) {
        float invM = 1.f / (float)M;
        float m = g_stats[tid] * invM;
        float var = g_stats[tid + 256] * invM - m * m;
        float r = rsqrtf(var + 1e-5f);
        float a = gamma[tid] * r;
        sa[tid] = a;
        sb[tid] = beta[tid] - m * a;
        __syncthreads();
    }

    wmma::fragment<wmma::accumulator, 16, 16, 16, float> acc[2][4];
    #pragma unroll
    for (int i = 0; i < 2; i++)
        #pragma unroll
        for (int j = 0; j < 4; j++) wmma::fill_fragment(acc[i][j], 0.f);

    int a_r0 = AHALF ? (tid >> 2) : (tid >> 3);
    int a_c0 = AHALF ? ((tid & 3) * 8) : ((tid & 7) * 4);

    float areg[8];
    auto load_A = [&](int k0) {
        if constexpr (AHALF) {
            const __half* Ah = (const __half*)Av;
            int gr = row0 + a_r0;
            uint4 u = make_uint4(0, 0, 0, 0);
            if (gr < M) u = *(const uint4*)(Ah + (size_t)gr * F + k0 * 32 + a_c0);
            __half2* hp = reinterpret_cast<__half2*>(&u);
            #pragma unroll
            for (int i = 0; i < 4; i++) {
                float2 p = __half22float2(hp[i]);
                areg[i * 2] = p.x;
                areg[i * 2 + 1] = p.y;
            }
        } else {
            const float* Af = (const float*)Av;
            int gr0 = row0 + a_r0, gr1 = row0 + a_r0 + 32;
            float4 v0 = (gr0 < M) ? *(const float4*)(Af + (size_t)gr0 * F + k0 * 32 + a_c0)
                                  : make_float4(0.f, 0.f, 0.f, 0.f);
            float4 v1 = (gr1 < M) ? *(const float4*)(Af + (size_t)gr1 * F + k0 * 32 + a_c0)
                                  : make_float4(0.f, 0.f, 0.f, 0.f);
            areg[0] = v0.x; areg[1] = v0.y; areg[2] = v0.z; areg[3] = v0.w;
            areg[4] = v1.x; areg[5] = v1.y; areg[6] = v1.z; areg[7] = v1.w;
        }
        if constexpr (BNRELU) {
            int c = k0 * 32 + a_c0;
            if constexpr (AHALF) {
                #pragma unroll
                for (int i = 0; i < 8; i++)
                    areg[i] = fmaxf(fmaf(areg[i], sa[c + i], sb[c + i]), 0.f);
            } else {
                #pragma unroll
                for (int i = 0; i < 4; i++) {
                    float ga = sa[c + i], gb = sb[c + i];
                    areg[i]     = fmaxf(fmaf(areg[i],     ga, gb), 0.f);
                    areg[i + 4] = fmaxf(fmaf(areg[i + 4], ga, gb), 0.f);
                }
            }
        }
    };
    auto sts_A = [&](__half* As) {
        if constexpr (AHALF) {
            __half2 h[4];
            #pragma unroll
            for (int i = 0; i < 4; i++)
                h[i] = __floats2half2_rn(areg[i * 2], areg[i * 2 + 1]);
            *(uint4*)(As + a_r0 * ALD_H + a_c0) = *reinterpret_cast<uint4*>(h);
        } else {
            __half2 h0[2], h1[2];
            h0[0] = __floats2half2_rn(areg[0], areg[1]);
            h0[1] = __floats2half2_rn(areg[2], areg[3]);
            h1[0] = __floats2half2_rn(areg[4], areg[5]);
            h1[1] = __floats2half2_rn(areg[6], areg[7]);
            *(uint2*)(As + a_r0 * ALD_H + a_c0) = *reinterpret_cast<uint2*>(h0);
            *(uint2*)(As + (a_r0 + 32) * ALD_H + a_c0) = *reinterpret_cast<uint2*>(h1);
        }
    };
    auto cpB = [&](__half* Bs, int k0) {
        uint32_t bbase = smem_u32(Bs);
        #pragma unroll
        for (int i = 0; i < 4; i++) {
            int idx = tid + i * 256;
            int r = idx >> 5;
            int c8 = (idx & 31) * 8;
            cp16(bbase + (uint32_t)(r * BLD_H + c8) * 2,
                 Wh + (size_t)(k0 * 32 + r) * F + c8);
        }
    };

    int buf = 0;
    load_A(0);
    sts_A(smh);
    cpB(smh + ASZ_H, 0);
    asm volatile("cp.async.commit_group;" ::: "memory");

    for (int k0 = 0; k0 < 8; k0++) {
        if (k0 < 7) load_A(k0 + 1);
        asm volatile("cp.async.wait_group 0;" ::: "memory");
        __syncthreads();
        __half* As = smh + buf * STAGE_H;
        __half* Bs = As + ASZ_H;
        if (k0 < 7) {
            __half* Asn = smh + (buf ^ 1) * STAGE_H;
            sts_A(Asn);
            cpB(Asn + ASZ_H, k0 + 1);
            asm volatile("cp.async.commit_group;" ::: "memory");
        }
        #pragma unroll
        for (int kk = 0; kk < 2; kk++) {
            wmma::fragment<wmma::matrix_a, 16, 16, 16, __half, wmma::row_major> af[2];
            wmma::fragment<wmma::matrix_b, 16, 16, 16, __half, wmma::row_major> bf[4];
            #pragma unroll
            for (int i = 0; i < 2; i++)
                wmma::load_matrix_sync(af[i], As + (warp_row * 32 + i * 16) * ALD_H + kk * 16, ALD_H);
            #pragma unroll
            for (int j = 0; j < 4; j++)
                wmma::load_matrix_sync(bf[j], Bs + (kk * 16) * BLD_H + warp_col * 64 + j * 16, BLD_H);
            #pragma unroll
            for (int i = 0; i < 2; i++)
                #pragma unroll
                for (int j = 0; j < 4; j++)
                    wmma::mma_sync(acc[i][j], af[i], bf[j], acc[i][j]);
        }
        __syncthreads();
        buf ^= 1;
    }

    // epilogue: frags -> smem(float) -> coalesced fp16 store
    float* ep = sm;
    #pragma unroll
    for (int i = 0; i < 2; i++)
        #pragma unroll
        for (int j = 0; j < 4; j++)
            wmma::store_matrix_sync(ep + (size_t)(warp_row * 32 + i * 16) * EPLD + warp_col * 64 + j * 16,
                                    acc[i][j], EPLD, wmma::mem_row_major);
    __syncthreads();

    #pragma unroll
    for (int it = 0; it < 8; it++) {
        int idx = tid + it * 256;
        int r = idx >> 5;
        int g = idx & 31;
        int grow = row0 + r;
        if (grow < M) {
            float4 v0 = *(float4*)(ep + r * EPLD + g * 8);
            float4 v1 = *(float4*)(ep + r * EPLD + g * 8 + 4);
            __half2 h[4];
            h[0] = __floats2half2_rn(v0.x, v0.y);
            h[1] = __floats2half2_rn(v0.z, v0.w);
            h[2] = __floats2half2_rn(v1.x, v1.y);
            h[3] = __floats2half2_rn(v1.z, v1.w);
            *(uint4*)(Ch + (size_t)grow * F + g * 8) = *reinterpret_cast<uint4*>(h);
        }
    }
}

// ---------------- SpMM: warp/row, ELL, explicit 8-deep gather prefetch ----------------
template <int OUT16, int STATS>
__global__ void __launch_bounds__(256)
k_spmm(const __half* __restrict__ Xh, void* __restrict__ Yv, int Nn) {
    __shared__ float ssum[256], ssumsq[256];
    int tid = threadIdx.x;
    if constexpr (STATS) {
        ssum[tid] = 0.f;
        ssumsq[tid] = 0.f;
        __syncthreads();
    }

    int row = (blockIdx.x * 256 + tid) >> 5;
    int lane = tid & 31;
    bool valid = (row < Nn);

    float acc[8];
    if (valid) {
        // self loop (row stays cached normally; it's re-gathered by neighbors)
        uint4 u = __ldg((const uint4*)(Xh + (size_t)row * F + lane * 8));
        {
            __half2* hp = reinterpret_cast<__half2*>(&u);
            #pragma unroll
            for (int i = 0; i < 4; i++) {
                float2 p = __half22float2(hp[i]);
                acc[i * 2] = p.x;
                acc[i * 2 + 1] = p.y;
            }
        }

        int deg = g_cnt[row];
        const uint2* eb = g_edge + (size_t)row * ELLW;
        const __half* Xl = Xh + lane * 8;
        for (int e = 0; e < deg; e += 32) {
            int m = deg - e;
            if (m > 32) m = 32;
            uint2 ed = make_uint2(0u, 0u);
            if (lane < m) ed = __ldcs(eb + e + lane);
            int j = 0;
            // full 8-edge micro-batches: ALL loads issued before ANY use (MLP=8)
            for (; j + 8 <= m; j += 8) {
                uint4 gbuf[8];
                float vbuf[8];
                #pragma unroll
                for (int k = 0; k < 8; k++) {
                    int cj = __shfl_sync(0xffffffffu, (int)ed.x, j + k);
                    vbuf[k] = __uint_as_float(__shfl_sync(0xffffffffu, ed.y, j + k));
                    gbuf[k] = __ldlu((const uint4*)(Xl + (size_t)cj * F));
                }
                #pragma unroll
                for (int k = 0; k < 8; k++) {
                    __half2* hp = reinterpret_cast<__half2*>(&gbuf[k]);
                    float vj = vbuf[k];
                    #pragma unroll
                    for (int i = 0; i < 4; i++) {
                        float2 q = __half22float2(hp[i]);
                        acc[i * 2]     = fmaf(vj, q.x, acc[i * 2]);
                        acc[i * 2 + 1] = fmaf(vj, q.y, acc[i * 2 + 1]);
                    }
                }
            }
            // remainder
            for (; j < m; j++) {
                int cj = __shfl_sync(0xffffffffu, (int)ed.x, j);
                float vj = __uint_as_float(__shfl_sync(0xffffffffu, ed.y, j));
                uint4 un = __ldlu((const uint4*)(Xl + (size_t)cj * F));
                __half2* hp = reinterpret_cast<__half2*>(&un);
                #pragma unroll
                for (int i = 0; i < 4; i++) {
                    float2 q = __half22float2(hp[i]);
                    acc[i * 2]     = fmaf(vj, q.x, acc[i * 2]);
                    acc[i * 2 + 1] = fmaf(vj, q.y, acc[i * 2 + 1]);
                }
            }
        }
        if constexpr (OUT16) {
            __half* Y = (__half*)Yv;
            __half2 h[4];
            #pragma unroll
            for (int i = 0; i < 4; i++)
                h[i] = __floats2half2_rn(acc[i * 2], acc[i * 2 + 1]);
            __stcs((uint4*)(Y + (size_t)row * F + lane * 8), *reinterpret_cast<uint4*>(h));
        } else {
            float* Y = (float*)Yv;
            float4 o0 = make_float4(acc[0], acc[1], acc[2], acc[3]);
            float4 o1 = make_float4(acc[4], acc[5], acc[6], acc[7]);
            __stcs((float4*)(Y + (size_t)row * F + lane * 8), o0);
            __stcs((float4*)(Y + (size_t)row * F + lane * 8 + 4), o1);
        }
    }

    if constexpr (STATS) {
        if (valid) {
            int cb = lane * 8;
            #pragma unroll
            for (int i = 0; i < 8; i++) {
                atomicAdd(&ssum[cb + i], acc[i]);
                atomicAdd(&ssumsq[cb + i], acc[i] * acc[i]);
            }
        }
        __syncthreads();
        atomicAdd(&g_stats[tid], ssum[tid]);
        atomicAdd(&g_stats[tid + 256], ssumsq[tid]);
    }
}

// ---------------- launch ----------------
extern "C" void kernel_launch(void* const* d_in, const int* in_sizes, int n_in,
                              void* d_out, int out_size) {
    const float* feature = (const float*)d_in[0];
    const int*   rows    = (const int*)d_in[1];
    const int*   cols    = (const int*)d_in[2];
    const float* vals    = (const float*)d_in[3];
    const float* W1      = (const float*)d_in[4];
    const float* W2      = (const float*)d_in[5];
    const float* gamma   = (const float*)d_in[6];
    const float* beta    = (const float*)d_in[7];
    float* out = (float*)d_out;

    int N_ = in_sizes[0] / F;
    int E_ = in_sizes[1];

    __half *p_H16, *p_Xh, *p_Wh;
    int* p_cnt;
    cudaGetSymbolAddress((void**)&p_H16, g_H16);
    cudaGetSymbolAddress((void**)&p_Xh, g_Xh);
    cudaGetSymbolAddress((void**)&p_Wh, g_Wh);
    cudaGetSymbolAddress((void**)&p_cnt, g_cnt);

    const int smem_bytes = 64 * EPLD * sizeof(float) > 2 * STAGE_H * (int)sizeof(__half)
                         ? 64 * EPLD * sizeof(float) : 2 * STAGE_H * (int)sizeof(__half);
    cudaFuncSetAttribute(k_gemm_wmma<0, 0>, cudaFuncAttributeMaxDynamicSharedMemorySize, smem_bytes);
    cudaFuncSetAttribute(k_gemm_wmma<1, 1>, cudaFuncAttributeMaxDynamicSharedMemorySize, smem_bytes);

    static cudaStream_t s2 = nullptr;
    static cudaEvent_t evF = nullptr, evJ = nullptr;
    if (!s2) {
        cudaStreamCreateWithFlags(&s2, cudaStreamNonBlocking);
        cudaEventCreateWithFlags(&evF, cudaEventDisableTiming);
        cudaEventCreateWithFlags(&evJ, cudaEventDisableTiming);
    }

    int gtiles = (N_ + 63) / 64;
    int spmm_blocks = (N_ * 32 + 255) / 256;

    // fork: single-kernel ELL build on s2, hidden under prep_w + GEMM1
    cudaEventRecord(evF, 0);
    cudaStreamWaitEvent(s2, evF, 0);
    cudaMemsetAsync(p_cnt, 0, (size_t)N_ * sizeof(int), s2);

    k_prep_w<<<F * F / 256, 256>>>(W1, W2);                                 // launch 1
    k_gemm_wmma<0, 0><<<gtiles, 256, smem_bytes>>>(feature, p_Wh, p_Xh, N_, gamma, beta); // 2

    k_ell<<<(E_ + 255) / 256, 256, 0, s2>>>(rows, cols, vals, E_);          // 3
    cudaEventRecord(evJ, s2);
    cudaStreamWaitEvent(0, evJ, 0);

    // H16 = (A+I)@support (fp16 out) + fused BN stats
    k_spmm<1, 1><<<spmm_blocks, 256>>>(p_Xh, p_H16, N_);                    // 4 <- ncu capture
    // Xh = relu(BN(H16)) @ W2   (BN finalize folded into prologue)
    k_gemm_wmma<1, 1><<<gtiles, 256, smem_bytes>>>(p_H16, p_Wh + F * F, p_Xh, N_, gamma, beta);
    // out = (A+I)@Xh  (fp32 out)
    k_spmm<0, 0><<<spmm_blocks, 256>>>(p_Xh, out, N_);
}

// round 14
// speedup vs baseline: 1.0379x; 1.0379x over previous
#include <cuda_runtime.h>
#include <cuda_bf16.h>
#include <cuda_fp16.h>
#include <mma.h>
#include <cstdint>
#include <math.h>

using namespace nvcuda;

#define F 256
#define MAXN 100000
#define MAXE 3200000
#define ELLW 128

// ---------------- device scratch ----------------
__device__ __half g_H16[(size_t)MAXN * F];      // SpMM1 output (fp16, read by GEMM2)
__device__ __half g_Xh[(size_t)MAXN * F];       // fp16 copy of current GEMM output
__device__ int   g_cnt[MAXN];                   // per-row edge count (ELL)
__device__ uint2 g_edge[(size_t)MAXN * ELLW];   // ELL: packed (col, val_bits)
__device__ float g_stats[2 * F];                // [0:256) sum, [256:512) sumsq
__device__ __half g_Wh[2 * F * F];              // W1, W2 pre-converted to fp16

__device__ __forceinline__ uint32_t smem_u32(const void* p) {
    uint32_t a;
    asm("{ .reg .u64 t; cvta.to.shared.u64 t, %1; cvt.u32.u64 %0, t; }" : "=r"(a) : "l"(p));
    return a;
}

// ---------------- ELL build (single kernel; cnt pre-zeroed by memset) ----------------
__global__ void k_ell(const int* __restrict__ rows, const int* __restrict__ cols,
                      const float* __restrict__ vals, int E) {
    int e = blockIdx.x * blockDim.x + threadIdx.x;
    if (e < E) {
        int r = __ldcs(rows + e);
        int pos = atomicAdd(&g_cnt[r], 1);
        g_edge[(size_t)r * ELLW + pos] = make_uint2((uint32_t)__ldcs(cols + e),
                                                    __float_as_uint(__ldcs(vals + e)));
    }
}

// ---------------- W convert to fp16 (+ zero stats) ----------------
__global__ void k_prep_w(const float* __restrict__ W1, const float* __restrict__ W2) {
    int i = blockIdx.x * blockDim.x + threadIdx.x;
    if (blockIdx.x == 0) { g_stats[threadIdx.x] = 0.f; g_stats[threadIdx.x + 256] = 0.f; }
    g_Wh[i]         = __float2half_rn(W1[i]);
    g_Wh[i + F * F] = __float2half_rn(W2[i]);
}

// ---------------- fp16 wmma GEMM (A: fp32 or fp16), fp16 output ----------------
#define ALD_H 40
#define BLD_H 264
#define ASZ_H (64 * ALD_H)
#define BSZ_H (32 * BLD_H)
#define STAGE_H (ASZ_H + BSZ_H)
#define EPLD 264

__device__ __forceinline__ void cp16(uint32_t dst, const void* src) {
    asm volatile("cp.async.ca.shared.global [%0], [%1], 16;" :: "r"(dst), "l"(src));
}

template <int AHALF, int BNRELU>
__global__ void __launch_bounds__(256)
k_gemm_wmma(const void* __restrict__ Av, const __half* __restrict__ Wh,
            __half* __restrict__ Ch, int M,
            const float* __restrict__ gamma, const float* __restrict__ beta) {
    extern __shared__ float sm[];
    __half* smh = reinterpret_cast<__half*>(sm);
    __shared__ float sa[256], sb[256];
    int tid = threadIdx.x;
    int wid = tid >> 5;
    int warp_row = wid >> 2;
    int warp_col = wid & 3;
    int row0 = blockIdx.x * 64;

    if constexpr (BNRELU) {
        float invM = 1.f / (float)M;
        float m = g_stats[tid] * invM;
        float var = g_stats[tid + 256] * invM - m * m;
        float r = rsqrtf(var + 1e-5f);
        float a = gamma[tid] * r;
        sa[tid] = a;
        sb[tid] = beta[tid] - m * a;
        __syncthreads();
    }

    wmma::fragment<wmma::accumulator, 16, 16, 16, float> acc[2][4];
    #pragma unroll
    for (int i = 0; i < 2; i++)
        #pragma unroll
        for (int j = 0; j < 4; j++) wmma::fill_fragment(acc[i][j], 0.f);

    int a_r0 = AHALF ? (tid >> 2) : (tid >> 3);
    int a_c0 = AHALF ? ((tid & 3) * 8) : ((tid & 7) * 4);

    float areg[8];
    auto load_A = [&](int k0) {
        if constexpr (AHALF) {
            const __half* Ah = (const __half*)Av;
            int gr = row0 + a_r0;
            uint4 u = make_uint4(0, 0, 0, 0);
            if (gr < M) u = *(const uint4*)(Ah + (size_t)gr * F + k0 * 32 + a_c0);
            __half2* hp = reinterpret_cast<__half2*>(&u);
            #pragma unroll
            for (int i = 0; i < 4; i++) {
                float2 p = __half22float2(hp[i]);
                areg[i * 2] = p.x;
                areg[i * 2 + 1] = p.y;
            }
        } else {
            const float* Af = (const float*)Av;
            int gr0 = row0 + a_r0, gr1 = row0 + a_r0 + 32;
            float4 v0 = (gr0 < M) ? *(const float4*)(Af + (size_t)gr0 * F + k0 * 32 + a_c0)
                                  : make_float4(0.f, 0.f, 0.f, 0.f);
            float4 v1 = (gr1 < M) ? *(const float4*)(Af + (size_t)gr1 * F + k0 * 32 + a_c0)
                                  : make_float4(0.f, 0.f, 0.f, 0.f);
            areg[0] = v0.x; areg[1] = v0.y; areg[2] = v0.z; areg[3] = v0.w;
            areg[4] = v1.x; areg[5] = v1.y; areg[6] = v1.z; areg[7] = v1.w;
        }
        if constexpr (BNRELU) {
            int c = k0 * 32 + a_c0;
            if constexpr (AHALF) {
                #pragma unroll
                for (int i = 0; i < 8; i++)
                    areg[i] = fmaxf(fmaf(areg[i], sa[c + i], sb[c + i]), 0.f);
            } else {
                #pragma unroll
                for (int i = 0; i < 4; i++) {
                    float ga = sa[c + i], gb = sb[c + i];
                    areg[i]     = fmaxf(fmaf(areg[i],     ga, gb), 0.f);
                    areg[i + 4] = fmaxf(fmaf(areg[i + 4], ga, gb), 0.f);
                }
            }
        }
    };
    auto sts_A = [&](__half* As) {
        if constexpr (AHALF) {
            __half2 h[4];
            #pragma unroll
            for (int i = 0; i < 4; i++)
                h[i] = __floats2half2_rn(areg[i * 2], areg[i * 2 + 1]);
            *(uint4*)(As + a_r0 * ALD_H + a_c0) = *reinterpret_cast<uint4*>(h);
        } else {
            __half2 h0[2], h1[2];
            h0[0] = __floats2half2_rn(areg[0], areg[1]);
            h0[1] = __floats2half2_rn(areg[2], areg[3]);
            h1[0] = __floats2half2_rn(areg[4], areg[5]);
            h1[1] = __floats2half2_rn(areg[6], areg[7]);
            *(uint2*)(As + a_r0 * ALD_H + a_c0) = *reinterpret_cast<uint2*>(h0);
            *(uint2*)(As + (a_r0 + 32) * ALD_H + a_c0) = *reinterpret_cast<uint2*>(h1);
        }
    };
    auto cpB = [&](__half* Bs, int k0) {
        uint32_t bbase = smem_u32(Bs);
        #pragma unroll
        for (int i = 0; i < 4; i++) {
            int idx = tid + i * 256;
            int r = idx >> 5;
            int c8 = (idx & 31) * 8;
            cp16(bbase + (uint32_t)(r * BLD_H + c8) * 2,
                 Wh + (size_t)(k0 * 32 + r) * F + c8);
        }
    };

    int buf = 0;
    load_A(0);
    sts_A(smh);
    cpB(smh + ASZ_H, 0);
    asm volatile("cp.async.commit_group;" ::: "memory");

    for (int k0 = 0; k0 < 8; k0++) {
        if (k0 < 7) load_A(k0 + 1);
        asm volatile("cp.async.wait_group 0;" ::: "memory");
        __syncthreads();
        __half* As = smh + buf * STAGE_H;
        __half* Bs = As + ASZ_H;
        if (k0 < 7) {
            __half* Asn = smh + (buf ^ 1) * STAGE_H;
            sts_A(Asn);
            cpB(Asn + ASZ_H, k0 + 1);
            asm volatile("cp.async.commit_group;" ::: "memory");
        }
        #pragma unroll
        for (int kk = 0; kk < 2; kk++) {
            wmma::fragment<wmma::matrix_a, 16, 16, 16, __half, wmma::row_major> af[2];
            wmma::fragment<wmma::matrix_b, 16, 16, 16, __half, wmma::row_major> bf[4];
            #pragma unroll
            for (int i = 0; i < 2; i++)
                wmma::load_matrix_sync(af[i], As + (warp_row * 32 + i * 16) * ALD_H + kk * 16, ALD_H);
            #pragma unroll
            for (int j = 0; j < 4; j++)
                wmma::load_matrix_sync(bf[j], Bs + (kk * 16) * BLD_H + warp_col * 64 + j * 16, BLD_H);
            #pragma unroll
            for (int i = 0; i < 2; i++)
                #pragma unroll
                for (int j = 0; j < 4; j++)
                    wmma::mma_sync(acc[i][j], af[i], bf[j], acc[i][j]);
        }
        __syncthreads();
        buf ^= 1;
    }

    // epilogue: frags -> smem(float) -> coalesced fp16 store
    float* ep = sm;
    #pragma unroll
    for (int i = 0; i < 2; i++)
        #pragma unroll
        for (int j = 0; j < 4; j++)
            wmma::store_matrix_sync(ep + (size_t)(warp_row * 32 + i * 16) * EPLD + warp_col * 64 + j * 16,
                                    acc[i][j], EPLD, wmma::mem_row_major);
    __syncthreads();

    #pragma unroll
    for (int it = 0; it < 8; it++) {
        int idx = tid + it * 256;
        int r = idx >> 5;
        int g = idx & 31;
        int grow = row0 + r;
        if (grow < M) {
            float4 v0 = *(float4*)(ep + r * EPLD + g * 8);
            float4 v1 = *(float4*)(ep + r * EPLD + g * 8 + 4);
            __half2 h[4];
            h[0] = __floats2half2_rn(v0.x, v0.y);
            h[1] = __floats2half2_rn(v0.z, v0.w);
            h[2] = __floats2half2_rn(v1.x, v1.y);
            h[3] = __floats2half2_rn(v1.z, v1.w);
            *(uint4*)(Ch + (size_t)grow * F + g * 8) = *reinterpret_cast<uint4*>(h);
        }
    }
}

// ---------------- SpMM: 2 warps/row, LDG.64 gathers, unroll-8 prefetch ----------------
template <int OUT16, int STATS>
__global__ void __launch_bounds__(256)
k_spmm(const __half* __restrict__ Xh, void* __restrict__ Yv, int Nn) {
    __shared__ float ssum[256], ssumsq[256];
    int tid = threadIdx.x;
    if constexpr (STATS) {
        ssum[tid] = 0.f;
        ssumsq[tid] = 0.f;
        __syncthreads();
    }

    int gw = (blockIdx.x * 256 + tid) >> 5;
    int row = gw >> 1;
    int half = gw & 1;
    int lane = tid & 31;
    bool valid = (row < Nn);

    float acc[4];
    if (valid) {
        const __half* Xq = Xh + half * 128 + lane * 4;    // this thread's 4-feature slice
        // self loop
        uint2 u = __ldg((const uint2*)(Xq + (size_t)row * F));
        {
            float2 p0 = __half22float2(*reinterpret_cast<const __half2*>(&u.x));
            float2 p1 = __half22float2(*reinterpret_cast<const __half2*>(&u.y));
            acc[0] = p0.x; acc[1] = p0.y; acc[2] = p1.x; acc[3] = p1.y;
        }

        int deg = g_cnt[row];
        const uint2* eb = g_edge + (size_t)row * ELLW;
        for (int e = 0; e < deg; e += 32) {
            int m = deg - e;
            if (m > 32) m = 32;
            uint2 ed = make_uint2(0u, 0u);
            if (lane < m) ed = __ldg(eb + e + lane);      // 2nd warp of row hits L1
            int j = 0;
            // 8-edge micro-batches: all gathers issued before any use (MLP=8)
            for (; j + 8 <= m; j += 8) {
                uint2 gbuf[8];
                float vbuf[8];
                #pragma unroll
                for (int k = 0; k < 8; k++) {
                    int cj = __shfl_sync(0xffffffffu, (int)ed.x, j + k);
                    vbuf[k] = __uint_as_float(__shfl_sync(0xffffffffu, ed.y, j + k));
                    gbuf[k] = __ldg((const uint2*)(Xq + (size_t)cj * F));
                }
                #pragma unroll
                for (int k = 0; k < 8; k++) {
                    float2 q0 = __half22float2(*reinterpret_cast<const __half2*>(&gbuf[k].x));
                    float2 q1 = __half22float2(*reinterpret_cast<const __half2*>(&gbuf[k].y));
                    float vj = vbuf[k];
                    acc[0] = fmaf(vj, q0.x, acc[0]);
                    acc[1] = fmaf(vj, q0.y, acc[1]);
                    acc[2] = fmaf(vj, q1.x, acc[2]);
                    acc[3] = fmaf(vj, q1.y, acc[3]);
                }
            }
            for (; j < m; j++) {
                int cj = __shfl_sync(0xffffffffu, (int)ed.x, j);
                float vj = __uint_as_float(__shfl_sync(0xffffffffu, ed.y, j));
                uint2 un = __ldg((const uint2*)(Xq + (size_t)cj * F));
                float2 q0 = __half22float2(*reinterpret_cast<const __half2*>(&un.x));
                float2 q1 = __half22float2(*reinterpret_cast<const __half2*>(&un.y));
                acc[0] = fmaf(vj, q0.x, acc[0]);
                acc[1] = fmaf(vj, q0.y, acc[1]);
                acc[2] = fmaf(vj, q1.x, acc[2]);
                acc[3] = fmaf(vj, q1.y, acc[3]);
            }
        }
        size_t obase = (size_t)row * F + half * 128 + lane * 4;
        if constexpr (OUT16) {
            __half* Y = (__half*)Yv;
            __half2 h[2];
            h[0] = __floats2half2_rn(acc[0], acc[1]);
            h[1] = __floats2half2_rn(acc[2], acc[3]);
            __stcs((float2*)(Y + obase), *reinterpret_cast<float2*>(h));
        } else {
            float* Y = (float*)Yv;
            __stcs((float4*)(Y + obase), make_float4(acc[0], acc[1], acc[2], acc[3]));
        }
    }

    if constexpr (STATS) {
        if (valid) {
            int cb = half * 128 + lane * 4;
            #pragma unroll
            for (int i = 0; i < 4; i++) {
                atomicAdd(&ssum[cb + i], acc[i]);
                atomicAdd(&ssumsq[cb + i], acc[i] * acc[i]);
            }
        }
        __syncthreads();
        atomicAdd(&g_stats[tid], ssum[tid]);
        atomicAdd(&g_stats[tid + 256], ssumsq[tid]);
    }
}

// ---------------- launch ----------------
extern "C" void kernel_launch(void* const* d_in, const int* in_sizes, int n_in,
                              void* d_out, int out_size) {
    const float* feature = (const float*)d_in[0];
    const int*   rows    = (const int*)d_in[1];
    const int*   cols    = (const int*)d_in[2];
    const float* vals    = (const float*)d_in[3];
    const float* W1      = (const float*)d_in[4];
    const float* W2      = (const float*)d_in[5];
    const float* gamma   = (const float*)d_in[6];
    const float* beta    = (const float*)d_in[7];
    float* out = (float*)d_out;

    int N_ = in_sizes[0] / F;
    int E_ = in_sizes[1];

    __half *p_H16, *p_Xh, *p_Wh;
    int* p_cnt;
    cudaGetSymbolAddress((void**)&p_H16, g_H16);
    cudaGetSymbolAddress((void**)&p_Xh, g_Xh);
    cudaGetSymbolAddress((void**)&p_Wh, g_Wh);
    cudaGetSymbolAddress((void**)&p_cnt, g_cnt);

    const int smem_bytes = 64 * EPLD * sizeof(float) > 2 * STAGE_H * (int)sizeof(__half)
                         ? 64 * EPLD * sizeof(float) : 2 * STAGE_H * (int)sizeof(__half);
    cudaFuncSetAttribute(k_gemm_wmma<0, 0>, cudaFuncAttributeMaxDynamicSharedMemorySize, smem_bytes);
    cudaFuncSetAttribute(k_gemm_wmma<1, 1>, cudaFuncAttributeMaxDynamicSharedMemorySize, smem_bytes);

    static cudaStream_t s2 = nullptr;
    static cudaEvent_t evF = nullptr, evJ = nullptr;
    if (!s2) {
        cudaStreamCreateWithFlags(&s2, cudaStreamNonBlocking);
        cudaEventCreateWithFlags(&evF, cudaEventDisableTiming);
        cudaEventCreateWithFlags(&evJ, cudaEventDisableTiming);
    }

    int gtiles = (N_ + 63) / 64;
    int spmm_blocks = (2 * N_ * 32 + 255) / 256;

    // fork: single-kernel ELL build on s2, hidden under prep_w + GEMM1
    cudaEventRecord(evF, 0);
    cudaStreamWaitEvent(s2, evF, 0);
    cudaMemsetAsync(p_cnt, 0, (size_t)N_ * sizeof(int), s2);

    k_prep_w<<<F * F / 256, 256>>>(W1, W2);                                 // launch 1
    k_gemm_wmma<0, 0><<<gtiles, 256, smem_bytes>>>(feature, p_Wh, p_Xh, N_, gamma, beta); // 2

    k_ell<<<(E_ + 255) / 256, 256, 0, s2>>>(rows, cols, vals, E_);          // 3
    cudaEventRecord(evJ, s2);
    cudaStreamWaitEvent(0, evJ, 0);

    // H16 = (A+I)@support (fp16 out) + fused BN stats
    k_spmm<1, 1><<<spmm_blocks, 256>>>(p_Xh, p_H16, N_);                    // 4 <- ncu capture
    // Xh = relu(BN(H16)) @ W2   (BN finalize folded into prologue)
    k_gemm_wmma<1, 1><<<gtiles, 256, smem_bytes>>>(p_H16, p_Wh + F * F, p_Xh, N_, gamma, beta);
    // out = (A+I)@Xh  (fp32 out)
    k_spmm<0, 0><<<spmm_blocks, 256>>>(p_Xh, out, N_);
}

// round 15
// speedup vs baseline: 1.2607x; 1.2147x over previous
#include <cuda_runtime.h>
#include <cuda_bf16.h>
#include <cuda_fp16.h>
#include <mma.h>
#include <cstdint>
#include <math.h>

using namespace nvcuda;

#define F 256
#define MAXN 100000
#define MAXE 3200000
#define ELLW 128

// ---------------- device scratch ----------------
__device__ __half g_H16[(size_t)MAXN * F];      // SpMM1 output (fp16, read by GEMM2)
__device__ __half g_Xh[(size_t)MAXN * F];       // fp16 copy of current GEMM output
__device__ int   g_cnt[MAXN];                   // per-row edge count (ELL)
__device__ uint2 g_edge[(size_t)MAXN * ELLW];   // ELL: packed (col, val_bits)
__device__ float g_stats[2 * F];                // [0:256) sum, [256:512) sumsq
__device__ __half g_Wh[2 * F * F];              // W1, W2 pre-converted to fp16

__device__ __forceinline__ uint32_t smem_u32(const void* p) {
    uint32_t a;
    asm("{ .reg .u64 t; cvta.to.shared.u64 t, %1; cvt.u32.u64 %0, t; }" : "=r"(a) : "l"(p));
    return a;
}

// ---------------- ELL build (single kernel; cnt pre-zeroed by memset) ----------------
__global__ void k_ell(const int* __restrict__ rows, const int* __restrict__ cols,
                      const float* __restrict__ vals, int E) {
    int e = blockIdx.x * blockDim.x + threadIdx.x;
    if (e < E) {
        int r = __ldcs(rows + e);
        int pos = atomicAdd(&g_cnt[r], 1);
        g_edge[(size_t)r * ELLW + pos] = make_uint2((uint32_t)__ldcs(cols + e),
                                                    __float_as_uint(__ldcs(vals + e)));
    }
}

// ---------------- W convert to fp16 (+ zero stats) ----------------
__global__ void k_prep_w(const float* __restrict__ W1, const float* __restrict__ W2) {
    int i = blockIdx.x * blockDim.x + threadIdx.x;
    if (blockIdx.x == 0) { g_stats[threadIdx.x] = 0.f; g_stats[threadIdx.x + 256] = 0.f; }
    g_Wh[i]         = __float2half_rn(W1[i]);
    g_Wh[i + F * F] = __float2half_rn(W2[i]);
}

// ---------------- fp16 wmma GEMM (A: fp32 or fp16), fp16 output ----------------
#define ALD_H 40
#define BLD_H 264
#define ASZ_H (64 * ALD_H)
#define BSZ_H (32 * BLD_H)
#define STAGE_H (ASZ_H + BSZ_H)
#define EPLD 264

__device__ __forceinline__ void cp16(uint32_t dst, const void* src) {
    asm volatile("cp.async.ca.shared.global [%0], [%1], 16;" :: "r"(dst), "l"(src));
}

template <int AHALF, int BNRELU>
__global__ void __launch_bounds__(256)
k_gemm_wmma(const void* __restrict__ Av, const __half* __restrict__ Wh,
            __half* __restrict__ Ch, int M,
            const float* __restrict__ gamma, const float* __restrict__ beta) {
    extern __shared__ float sm[];
    __half* smh = reinterpret_cast<__half*>(sm);
    __shared__ float sa[256], sb[256];
    int tid = threadIdx.x;
    int wid = tid >> 5;
    int warp_row = wid >> 2;
    int warp_col = wid & 3;
    int row0 = blockIdx.x * 64;

    if constexpr (BNRELU) {
        float invM = 1.f / (float)M;
        float m = g_stats[tid] * invM;
        float var = g_stats[tid + 256] * invM - m * m;
        float r = rsqrtf(var + 1e-5f);
        float a = gamma[tid] * r;
        sa[tid] = a;
        sb[tid] = beta[tid] - m * a;
        __syncthreads();
    }

    wmma::fragment<wmma::accumulator, 16, 16, 16, float> acc[2][4];
    #pragma unroll
    for (int i = 0; i < 2; i++)
        #pragma unroll
        for (int j = 0; j < 4; j++) wmma::fill_fragment(acc[i][j], 0.f);

    int a_r0 = AHALF ? (tid >> 2) : (tid >> 3);
    int a_c0 = AHALF ? ((tid & 3) * 8) : ((tid & 7) * 4);

    float areg[8];
    auto load_A = [&](int k0) {
        if constexpr (AHALF) {
            const __half* Ah = (const __half*)Av;
            int gr = row0 + a_r0;
            uint4 u = make_uint4(0, 0, 0, 0);
            if (gr < M) u = *(const uint4*)(Ah + (size_t)gr * F + k0 * 32 + a_c0);
            __half2* hp = reinterpret_cast<__half2*>(&u);
            #pragma unroll
            for (int i = 0; i < 4; i++) {
                float2 p = __half22float2(hp[i]);
                areg[i * 2] = p.x;
                areg[i * 2 + 1] = p.y;
            }
        } else {
            const float* Af = (const float*)Av;
            int gr0 = row0 + a_r0, gr1 = row0 + a_r0 + 32;
            float4 v0 = (gr0 < M) ? *(const float4*)(Af + (size_t)gr0 * F + k0 * 32 + a_c0)
                                  : make_float4(0.f, 0.f, 0.f, 0.f);
            float4 v1 = (gr1 < M) ? *(const float4*)(Af + (size_t)gr1 * F + k0 * 32 + a_c0)
                                  : make_float4(0.f, 0.f, 0.f, 0.f);
            areg[0] = v0.x; areg[1] = v0.y; areg[2] = v0.z; areg[3] = v0.w;
            areg[4] = v1.x; areg[5] = v1.y; areg[6] = v1.z; areg[7] = v1.w;
        }
        if constexpr (BNRELU) {
            int c = k0 * 32 + a_c0;
            if constexpr (AHALF) {
                #pragma unroll
                for (int i = 0; i < 8; i++)
                    areg[i] = fmaxf(fmaf(areg[i], sa[c + i], sb[c + i]), 0.f);
            } else {
                #pragma unroll
                for (int i = 0; i < 4; i++) {
                    float ga = sa[c + i], gb = sb[c + i];
                    areg[i]     = fmaxf(fmaf(areg[i],     ga, gb), 0.f);
                    areg[i + 4] = fmaxf(fmaf(areg[i + 4], ga, gb), 0.f);
                }
            }
        }
    };
    auto sts_A = [&](__half* As) {
        if constexpr (AHALF) {
            __half2 h[4];
            #pragma unroll
            for (int i = 0; i < 4; i++)
                h[i] = __floats2half2_rn(areg[i * 2], areg[i * 2 + 1]);
            *(uint4*)(As + a_r0 * ALD_H + a_c0) = *reinterpret_cast<uint4*>(h);
        } else {
            __half2 h0[2], h1[2];
            h0[0] = __floats2half2_rn(areg[0], areg[1]);
            h0[1] = __floats2half2_rn(areg[2], areg[3]);
            h1[0] = __floats2half2_rn(areg[4], areg[5]);
            h1[1] = __floats2half2_rn(areg[6], areg[7]);
            *(uint2*)(As + a_r0 * ALD_H + a_c0) = *reinterpret_cast<uint2*>(h0);
            *(uint2*)(As + (a_r0 + 32) * ALD_H + a_c0) = *reinterpret_cast<uint2*>(h1);
        }
    };
    auto cpB = [&](__half* Bs, int k0) {
        uint32_t bbase = smem_u32(Bs);
        #pragma unroll
        for (int i = 0; i < 4; i++) {
            int idx = tid + i * 256;
            int r = idx >> 5;
            int c8 = (idx & 31) * 8;
            cp16(bbase + (uint32_t)(r * BLD_H + c8) * 2,
                 Wh + (size_t)(k0 * 32 + r) * F + c8);
        }
    };

    int buf = 0;
    load_A(0);
    sts_A(smh);
    cpB(smh + ASZ_H, 0);
    asm volatile("cp.async.commit_group;" ::: "memory");

    for (int k0 = 0; k0 < 8; k0++) {
        if (k0 < 7) load_A(k0 + 1);
        asm volatile("cp.async.wait_group 0;" ::: "memory");
        __syncthreads();
        __half* As = smh + buf * STAGE_H;
        __half* Bs = As + ASZ_H;
        if (k0 < 7) {
            __half* Asn = smh + (buf ^ 1) * STAGE_H;
            sts_A(Asn);
            cpB(Asn + ASZ_H, k0 + 1);
            asm volatile("cp.async.commit_group;" ::: "memory");
        }
        #pragma unroll
        for (int kk = 0; kk < 2; kk++) {
            wmma::fragment<wmma::matrix_a, 16, 16, 16, __half, wmma::row_major> af[2];
            wmma::fragment<wmma::matrix_b, 16, 16, 16, __half, wmma::row_major> bf[4];
            #pragma unroll
            for (int i = 0; i < 2; i++)
                wmma::load_matrix_sync(af[i], As + (warp_row * 32 + i * 16) * ALD_H + kk * 16, ALD_H);
            #pragma unroll
            for (int j = 0; j < 4; j++)
                wmma::load_matrix_sync(bf[j], Bs + (kk * 16) * BLD_H + warp_col * 64 + j * 16, BLD_H);
            #pragma unroll
            for (int i = 0; i < 2; i++)
                #pragma unroll
                for (int j = 0; j < 4; j++)
                    wmma::mma_sync(acc[i][j], af[i], bf[j], acc[i][j]);
        }
        __syncthreads();
        buf ^= 1;
    }

    // epilogue: frags -> smem(float) -> coalesced fp16 store
    float* ep = sm;
    #pragma unroll
    for (int i = 0; i < 2; i++)
        #pragma unroll
        for (int j = 0; j < 4; j++)
            wmma::store_matrix_sync(ep + (size_t)(warp_row * 32 + i * 16) * EPLD + warp_col * 64 + j * 16,
                                    acc[i][j], EPLD, wmma::mem_row_major);
    __syncthreads();

    #pragma unroll
    for (int it = 0; it < 8; it++) {
        int idx = tid + it * 256;
        int r = idx >> 5;
        int g = idx & 31;
        int grow = row0 + r;
        if (grow < M) {
            float4 v0 = *(float4*)(ep + r * EPLD + g * 8);
            float4 v1 = *(float4*)(ep + r * EPLD + g * 8 + 4);
            __half2 h[4];
            h[0] = __floats2half2_rn(v0.x, v0.y);
            h[1] = __floats2half2_rn(v0.z, v0.w);
            h[2] = __floats2half2_rn(v1.x, v1.y);
            h[3] = __floats2half2_rn(v1.z, v1.w);
            *(uint4*)(Ch + (size_t)grow * F + g * 8) = *reinterpret_cast<uint4*>(h);
        }
    }
}

// ---------------- SpMM: warp/row, 4x LDG.32 per gather (single-wavefront loads) ----------------
template <int OUT16, int STATS>
__global__ void __launch_bounds__(256)
k_spmm(const __half* __restrict__ Xh, void* __restrict__ Yv, int Nn) {
    __shared__ float ssum[256], ssumsq[256];
    int tid = threadIdx.x;
    if constexpr (STATS) {
        ssum[tid] = 0.f;
        ssumsq[tid] = 0.f;
        __syncthreads();
    }

    int row = (blockIdx.x * 256 + tid) >> 5;
    int lane = tid & 31;
    bool valid = (row < Nn);

    float acc[8];   // features q*64 + lane*2 + {0,1}, q = 0..3
    if (valid) {
        const __half* Xq = Xh + lane * 2;    // + q*64 + row*F
        // self loop: 4 single-wavefront loads
        {
            uint32_t s[4];
            #pragma unroll
            for (int q = 0; q < 4; q++)
                s[q] = __ldg((const uint32_t*)(Xq + (size_t)row * F + q * 64));
            #pragma unroll
            for (int q = 0; q < 4; q++) {
                float2 p = __half22float2(*reinterpret_cast<const __half2*>(&s[q]));
                acc[q * 2] = p.x;
                acc[q * 2 + 1] = p.y;
            }
        }

        int deg = g_cnt[row];
        const uint2* eb = g_edge + (size_t)row * ELLW;
        for (int e = 0; e < deg; e += 32) {
            int m = deg - e;
            if (m > 32) m = 32;
            uint2 ed = make_uint2(0u, 0u);
            if (lane < m) ed = __ldg(eb + e + lane);
            int j = 0;
            // 4-edge micro-batches: 16 single-wavefront loads in flight
            for (; j + 4 <= m; j += 4) {
                uint32_t gbuf[4][4];
                float vbuf[4];
                #pragma unroll
                for (int k = 0; k < 4; k++) {
                    int cj = __shfl_sync(0xffffffffu, (int)ed.x, j + k);
                    vbuf[k] = __uint_as_float(__shfl_sync(0xffffffffu, ed.y, j + k));
                    const __half* src = Xq + (size_t)cj * F;
                    #pragma unroll
                    for (int q = 0; q < 4; q++)
                        gbuf[k][q] = __ldg((const uint32_t*)(src + q * 64));
                }
                #pragma unroll
                for (int k = 0; k < 4; k++) {
                    float vj = vbuf[k];
                    #pragma unroll
                    for (int q = 0; q < 4; q++) {
                        float2 p = __half22float2(*reinterpret_cast<const __half2*>(&gbuf[k][q]));
                        acc[q * 2]     = fmaf(vj, p.x, acc[q * 2]);
                        acc[q * 2 + 1] = fmaf(vj, p.y, acc[q * 2 + 1]);
                    }
                }
            }
            for (; j < m; j++) {
                int cj = __shfl_sync(0xffffffffu, (int)ed.x, j);
                float vj = __uint_as_float(__shfl_sync(0xffffffffu, ed.y, j));
                const __half* src = Xq + (size_t)cj * F;
                uint32_t g2[4];
                #pragma unroll
                for (int q = 0; q < 4; q++)
                    g2[q] = __ldg((const uint32_t*)(src + q * 64));
                #pragma unroll
                for (int q = 0; q < 4; q++) {
                    float2 p = __half22float2(*reinterpret_cast<const __half2*>(&g2[q]));
                    acc[q * 2]     = fmaf(vj, p.x, acc[q * 2]);
                    acc[q * 2 + 1] = fmaf(vj, p.y, acc[q * 2 + 1]);
                }
            }
        }
        // store: per quarter, 4B/lane coalesced (fp16) or 8B/lane (fp32)
        if constexpr (OUT16) {
            __half* Y = (__half*)Yv;
            #pragma unroll
            for (int q = 0; q < 4; q++) {
                __half2 h = __floats2half2_rn(acc[q * 2], acc[q * 2 + 1]);
                __stcs((uint32_t*)(Y + (size_t)row * F + q * 64 + lane * 2),
                       *reinterpret_cast<uint32_t*>(&h));
            }
        } else {
            float* Y = (float*)Yv;
            #pragma unroll
            for (int q = 0; q < 4; q++)
                __stcs((float2*)(Y + (size_t)row * F + q * 64 + lane * 2),
                       make_float2(acc[q * 2], acc[q * 2 + 1]));
        }
    }

    if constexpr (STATS) {
        if (valid) {
            #pragma unroll
            for (int q = 0; q < 4; q++) {
                int cb = q * 64 + lane * 2;
                atomicAdd(&ssum[cb], acc[q * 2]);
                atomicAdd(&ssum[cb + 1], acc[q * 2 + 1]);
                atomicAdd(&ssumsq[cb], acc[q * 2] * acc[q * 2]);
                atomicAdd(&ssumsq[cb + 1], acc[q * 2 + 1] * acc[q * 2 + 1]);
            }
        }
        __syncthreads();
        atomicAdd(&g_stats[tid], ssum[tid]);
        atomicAdd(&g_stats[tid + 256], ssumsq[tid]);
    }
}

// ---------------- launch ----------------
extern "C" void kernel_launch(void* const* d_in, const int* in_sizes, int n_in,
                              void* d_out, int out_size) {
    const float* feature = (const float*)d_in[0];
    const int*   rows    = (const int*)d_in[1];
    const int*   cols    = (const int*)d_in[2];
    const float* vals    = (const float*)d_in[3];
    const float* W1      = (const float*)d_in[4];
    const float* W2      = (const float*)d_in[5];
    const float* gamma   = (const float*)d_in[6];
    const float* beta    = (const float*)d_in[7];
    float* out = (float*)d_out;

    int N_ = in_sizes[0] / F;
    int E_ = in_sizes[1];

    __half *p_H16, *p_Xh, *p_Wh;
    int* p_cnt;
    cudaGetSymbolAddress((void**)&p_H16, g_H16);
    cudaGetSymbolAddress((void**)&p_Xh, g_Xh);
    cudaGetSymbolAddress((void**)&p_Wh, g_Wh);
    cudaGetSymbolAddress((void**)&p_cnt, g_cnt);

    const int smem_bytes = 64 * EPLD * sizeof(float) > 2 * STAGE_H * (int)sizeof(__half)
                         ? 64 * EPLD * sizeof(float) : 2 * STAGE_H * (int)sizeof(__half);
    cudaFuncSetAttribute(k_gemm_wmma<0, 0>, cudaFuncAttributeMaxDynamicSharedMemorySize, smem_bytes);
    cudaFuncSetAttribute(k_gemm_wmma<1, 1>, cudaFuncAttributeMaxDynamicSharedMemorySize, smem_bytes);

    static cudaStream_t s2 = nullptr;
    static cudaEvent_t evF = nullptr, evJ = nullptr;
    if (!s2) {
        cudaStreamCreateWithFlags(&s2, cudaStreamNonBlocking);
        cudaEventCreateWithFlags(&evF, cudaEventDisableTiming);
        cudaEventCreateWithFlags(&evJ, cudaEventDisableTiming);
    }

    int gtiles = (N_ + 63) / 64;
    int spmm_blocks = (N_ * 32 + 255) / 256;

    // fork: single-kernel ELL build on s2, hidden under prep_w + GEMM1
    cudaEventRecord(evF, 0);
    cudaStreamWaitEvent(s2, evF, 0);
    cudaMemsetAsync(p_cnt, 0, (size_t)N_ * sizeof(int), s2);

    k_prep_w<<<F * F / 256, 256>>>(W1, W2);                                 // launch 1
    k_gemm_wmma<0, 0><<<gtiles, 256, smem_bytes>>>(feature, p_Wh, p_Xh, N_, gamma, beta); // 2

    k_ell<<<(E_ + 255) / 256, 256, 0, s2>>>(rows, cols, vals, E_);          // 3
    cudaEventRecord(evJ, s2);
    cudaStreamWaitEvent(0, evJ, 0);

    // H16 = (A+I)@support (fp16 out) + fused BN stats
    k_spmm<1, 1><<<spmm_blocks, 256>>>(p_Xh, p_H16, N_);                    // 4 <- ncu capture
    // Xh = relu(BN(H16)) @ W2   (BN finalize folded into prologue)
    k_gemm_wmma<1, 1><<<gtiles, 256, smem_bytes>>>(p_H16, p_Wh + F * F, p_Xh, N_, gamma, beta);
    // out = (A+I)@Xh  (fp32 out)
    k_spmm<0, 0><<<spmm_blocks, 256>>>(p_Xh, out, N_);
}

// round 16
// speedup vs baseline: 1.3030x; 1.0336x over previous
#include <cuda_runtime.h>
#include <cuda_bf16.h>
#include <cuda_fp16.h>
#include <mma.h>
#include <cstdint>
#include <math.h>

using namespace nvcuda;

#define F 256
#define MAXN 100000
#define MAXE 3200000
#define ELLW 128

// ---------------- device scratch ----------------
__device__ __half g_H16[(size_t)MAXN * F];      // SpMM1 output (fp16, read by GEMM2)
__device__ __half g_Xh[(size_t)MAXN * F];       // fp16 copy of current GEMM output
__device__ int   g_cnt[MAXN];                   // per-row edge count (ELL)
__device__ uint2 g_edge[(size_t)MAXN * ELLW];   // ELL: packed (col, val_bits)
__device__ float g_stats[2 * F];                // [0:256) sum, [256:512) sumsq
__device__ __half g_Wh[2 * F * F];              // W1, W2 pre-converted to fp16

__device__ __forceinline__ uint32_t smem_u32(const void* p) {
    uint32_t a;
    asm("{ .reg .u64 t; cvta.to.shared.u64 t, %1; cvt.u32.u64 %0, t; }" : "=r"(a) : "l"(p));
    return a;
}

// ---------------- ELL build (single kernel; cnt pre-zeroed by memset) ----------------
__global__ void k_ell(const int* __restrict__ rows, const int* __restrict__ cols,
                      const float* __restrict__ vals, int E) {
    int e = blockIdx.x * blockDim.x + threadIdx.x;
    if (e < E) {
        int r = __ldcs(rows + e);
        int pos = atomicAdd(&g_cnt[r], 1);
        g_edge[(size_t)r * ELLW + pos] = make_uint2((uint32_t)__ldcs(cols + e),
                                                    __float_as_uint(__ldcs(vals + e)));
    }
}

// ---------------- W convert to fp16 (+ zero stats) ----------------
__global__ void k_prep_w(const float* __restrict__ W1, const float* __restrict__ W2) {
    int i = blockIdx.x * blockDim.x + threadIdx.x;
    if (blockIdx.x == 0) { g_stats[threadIdx.x] = 0.f; g_stats[threadIdx.x + 256] = 0.f; }
    g_Wh[i]         = __float2half_rn(W1[i]);
    g_Wh[i + F * F] = __float2half_rn(W2[i]);
}

// ---------------- fp16 wmma GEMM (A: fp32 or fp16), fp16 output ----------------
#define ALD_H 40
#define BLD_H 264
#define ASZ_H (64 * ALD_H)
#define BSZ_H (32 * BLD_H)
#define STAGE_H (ASZ_H + BSZ_H)
#define EPLD 264

__device__ __forceinline__ void cp16(uint32_t dst, const void* src) {
    asm volatile("cp.async.ca.shared.global [%0], [%1], 16;" :: "r"(dst), "l"(src));
}

template <int AHALF, int BNRELU>
__global__ void __launch_bounds__(256)
k_gemm_wmma(const void* __restrict__ Av, const __half* __restrict__ Wh,
            __half* __restrict__ Ch, int M,
            const float* __restrict__ gamma, const float* __restrict__ beta) {
    extern __shared__ float sm[];
    __half* smh = reinterpret_cast<__half*>(sm);
    __shared__ float sa[256], sb[256];
    int tid = threadIdx.x;
    int wid = tid >> 5;
    int warp_row = wid >> 2;
    int warp_col = wid & 3;
    int row0 = blockIdx.x * 64;

    if constexpr (BNRELU) {
        float invM = 1.f / (float)M;
        float m = g_stats[tid] * invM;
        float var = g_stats[tid + 256] * invM - m * m;
        float r = rsqrtf(var + 1e-5f);
        float a = gamma[tid] * r;
        sa[tid] = a;
        sb[tid] = beta[tid] - m * a;
        __syncthreads();
    }

    wmma::fragment<wmma::accumulator, 16, 16, 16, float> acc[2][4];
    #pragma unroll
    for (int i = 0; i < 2; i++)
        #pragma unroll
        for (int j = 0; j < 4; j++) wmma::fill_fragment(acc[i][j], 0.f);

    int a_r0 = AHALF ? (tid >> 2) : (tid >> 3);
    int a_c0 = AHALF ? ((tid & 3) * 8) : ((tid & 7) * 4);

    float areg[8];
    auto load_A = [&](int k0) {
        if constexpr (AHALF) {
            const __half* Ah = (const __half*)Av;
            int gr = row0 + a_r0;
            uint4 u = make_uint4(0, 0, 0, 0);
            if (gr < M) u = *(const uint4*)(Ah + (size_t)gr * F + k0 * 32 + a_c0);
            __half2* hp = reinterpret_cast<__half2*>(&u);
            #pragma unroll
            for (int i = 0; i < 4; i++) {
                float2 p = __half22float2(hp[i]);
                areg[i * 2] = p.x;
                areg[i * 2 + 1] = p.y;
            }
        } else {
            const float* Af = (const float*)Av;
            int gr0 = row0 + a_r0, gr1 = row0 + a_r0 + 32;
            float4 v0 = (gr0 < M) ? *(const float4*)(Af + (size_t)gr0 * F + k0 * 32 + a_c0)
                                  : make_float4(0.f, 0.f, 0.f, 0.f);
            float4 v1 = (gr1 < M) ? *(const float4*)(Af + (size_t)gr1 * F + k0 * 32 + a_c0)
                                  : make_float4(0.f, 0.f, 0.f, 0.f);
            areg[0] = v0.x; areg[1] = v0.y; areg[2] = v0.z; areg[3] = v0.w;
            areg[4] = v1.x; areg[5] = v1.y; areg[6] = v1.z; areg[7] = v1.w;
        }
        if constexpr (BNRELU) {
            int c = k0 * 32 + a_c0;
            if constexpr (AHALF) {
                #pragma unroll
                for (int i = 0; i < 8; i++)
                    areg[i] = fmaxf(fmaf(areg[i], sa[c + i], sb[c + i]), 0.f);
            } else {
                #pragma unroll
                for (int i = 0; i < 4; i++) {
                    float ga = sa[c + i], gb = sb[c + i];
                    areg[i]     = fmaxf(fmaf(areg[i],     ga, gb), 0.f);
                    areg[i + 4] = fmaxf(fmaf(areg[i + 4], ga, gb), 0.f);
                }
            }
        }
    };
    auto sts_A = [&](__half* As) {
        if constexpr (AHALF) {
            __half2 h[4];
            #pragma unroll
            for (int i = 0; i < 4; i++)
                h[i] = __floats2half2_rn(areg[i * 2], areg[i * 2 + 1]);
            *(uint4*)(As + a_r0 * ALD_H + a_c0) = *reinterpret_cast<uint4*>(h);
        } else {
            __half2 h0[2], h1[2];
            h0[0] = __floats2half2_rn(areg[0], areg[1]);
            h0[1] = __floats2half2_rn(areg[2], areg[3]);
            h1[0] = __floats2half2_rn(areg[4], areg[5]);
            h1[1] = __floats2half2_rn(areg[6], areg[7]);
            *(uint2*)(As + a_r0 * ALD_H + a_c0) = *reinterpret_cast<uint2*>(h0);
            *(uint2*)(As + (a_r0 + 32) * ALD_H + a_c0) = *reinterpret_cast<uint2*>(h1);
        }
    };
    auto cpB = [&](__half* Bs, int k0) {
        uint32_t bbase = smem_u32(Bs);
        #pragma unroll
        for (int i = 0; i < 4; i++) {
            int idx = tid + i * 256;
            int r = idx >> 5;
            int c8 = (idx & 31) * 8;
            cp16(bbase + (uint32_t)(r * BLD_H + c8) * 2,
                 Wh + (size_t)(k0 * 32 + r) * F + c8);
        }
    };

    int buf = 0;
    load_A(0);
    sts_A(smh);
    cpB(smh + ASZ_H, 0);
    asm volatile("cp.async.commit_group;" ::: "memory");

    for (int k0 = 0; k0 < 8; k0++) {
        if (k0 < 7) load_A(k0 + 1);
        asm volatile("cp.async.wait_group 0;" ::: "memory");
        __syncthreads();
        __half* As = smh + buf * STAGE_H;
        __half* Bs = As + ASZ_H;
        if (k0 < 7) {
            __half* Asn = smh + (buf ^ 1) * STAGE_H;
            sts_A(Asn);
            cpB(Asn + ASZ_H, k0 + 1);
            asm volatile("cp.async.commit_group;" ::: "memory");
        }
        #pragma unroll
        for (int kk = 0; kk < 2; kk++) {
            wmma::fragment<wmma::matrix_a, 16, 16, 16, __half, wmma::row_major> af[2];
            wmma::fragment<wmma::matrix_b, 16, 16, 16, __half, wmma::row_major> bf[4];
            #pragma unroll
            for (int i = 0; i < 2; i++)
                wmma::load_matrix_sync(af[i], As + (warp_row * 32 + i * 16) * ALD_H + kk * 16, ALD_H);
            #pragma unroll
            for (int j = 0; j < 4; j++)
                wmma::load_matrix_sync(bf[j], Bs + (kk * 16) * BLD_H + warp_col * 64 + j * 16, BLD_H);
            #pragma unroll
            for (int i = 0; i < 2; i++)
                #pragma unroll
                for (int j = 0; j < 4; j++)
                    wmma::mma_sync(acc[i][j], af[i], bf[j], acc[i][j]);
        }
        __syncthreads();
        buf ^= 1;
    }

    // epilogue: frags -> smem(float) -> coalesced fp16 store
    float* ep = sm;
    #pragma unroll
    for (int i = 0; i < 2; i++)
        #pragma unroll
        for (int j = 0; j < 4; j++)
            wmma::store_matrix_sync(ep + (size_t)(warp_row * 32 + i * 16) * EPLD + warp_col * 64 + j * 16,
                                    acc[i][j], EPLD, wmma::mem_row_major);
    __syncthreads();

    #pragma unroll
    for (int it = 0; it < 8; it++) {
        int idx = tid + it * 256;
        int r = idx >> 5;
        int g = idx & 31;
        int grow = row0 + r;
        if (grow < M) {
            float4 v0 = *(float4*)(ep + r * EPLD + g * 8);
            float4 v1 = *(float4*)(ep + r * EPLD + g * 8 + 4);
            __half2 h[4];
            h[0] = __floats2half2_rn(v0.x, v0.y);
            h[1] = __floats2half2_rn(v0.z, v0.w);
            h[2] = __floats2half2_rn(v1.x, v1.y);
            h[3] = __floats2half2_rn(v1.z, v1.w);
            *(uint4*)(Ch + (size_t)grow * F + g * 8) = *reinterpret_cast<uint4*>(h);
        }
    }
}

// ---------------- SpMM: warp/row, 4x LDG.32 gathers, 6 CTAs/SM ----------------
template <int OUT16, int STATS>
__global__ void __launch_bounds__(256, 6)
k_spmm(const __half* __restrict__ Xh, void* __restrict__ Yv, int Nn) {
    __shared__ float ssum[256], ssumsq[256];
    int tid = threadIdx.x;
    if constexpr (STATS) {
        ssum[tid] = 0.f;
        ssumsq[tid] = 0.f;
        __syncthreads();
    }

    int row = (blockIdx.x * 256 + tid) >> 5;
    int lane = tid & 31;
    bool valid = (row < Nn);

    float acc[8];   // features q*64 + lane*2 + {0,1}, q = 0..3
    if (valid) {
        const __half* Xq = Xh + lane * 2;    // + q*64 + row*F
        // self loop: 4 single-wavefront loads
        {
            uint32_t s[4];
            #pragma unroll
            for (int q = 0; q < 4; q++)
                s[q] = __ldg((const uint32_t*)(Xq + (size_t)row * F + q * 64));
            #pragma unroll
            for (int q = 0; q < 4; q++) {
                float2 p = __half22float2(*reinterpret_cast<const __half2*>(&s[q]));
                acc[q * 2] = p.x;
                acc[q * 2 + 1] = p.y;
            }
        }

        int deg = g_cnt[row];
        const uint2* eb = g_edge + (size_t)row * ELLW;
        for (int e = 0; e < deg; e += 32) {
            int m = deg - e;
            if (m > 32) m = 32;
            uint2 ed = make_uint2(0u, 0u);
            if (lane < m) ed = __ldg(eb + e + lane);
            int j = 0;
            // 4-edge micro-batches: 16 single-wavefront loads in flight;
            // edge weight shuffled lazily in the use phase (saves vbuf regs)
            for (; j + 4 <= m; j += 4) {
                uint32_t gbuf[4][4];
                #pragma unroll
                for (int k = 0; k < 4; k++) {
                    int cj = __shfl_sync(0xffffffffu, (int)ed.x, j + k);
                    const __half* src = Xq + (size_t)cj * F;
                    #pragma unroll
                    for (int q = 0; q < 4; q++)
                        gbuf[k][q] = __ldg((const uint32_t*)(src + q * 64));
                }
                #pragma unroll
                for (int k = 0; k < 4; k++) {
                    float vj = __uint_as_float(__shfl_sync(0xffffffffu, ed.y, j + k));
                    #pragma unroll
                    for (int q = 0; q < 4; q++) {
                        float2 p = __half22float2(*reinterpret_cast<const __half2*>(&gbuf[k][q]));
                        acc[q * 2]     = fmaf(vj, p.x, acc[q * 2]);
                        acc[q * 2 + 1] = fmaf(vj, p.y, acc[q * 2 + 1]);
                    }
                }
            }
            for (; j < m; j++) {
                int cj = __shfl_sync(0xffffffffu, (int)ed.x, j);
                float vj = __uint_as_float(__shfl_sync(0xffffffffu, ed.y, j));
                const __half* src = Xq + (size_t)cj * F;
                uint32_t g2[4];
                #pragma unroll
                for (int q = 0; q < 4; q++)
                    g2[q] = __ldg((const uint32_t*)(src + q * 64));
                #pragma unroll
                for (int q = 0; q < 4; q++) {
                    float2 p = __half22float2(*reinterpret_cast<const __half2*>(&g2[q]));
                    acc[q * 2]     = fmaf(vj, p.x, acc[q * 2]);
                    acc[q * 2 + 1] = fmaf(vj, p.y, acc[q * 2 + 1]);
                }
            }
        }
        // store: per quarter, 4B/lane coalesced (fp16) or 8B/lane (fp32)
        if constexpr (OUT16) {
            __half* Y = (__half*)Yv;
            #pragma unroll
            for (int q = 0; q < 4; q++) {
                __half2 h = __floats2half2_rn(acc[q * 2], acc[q * 2 + 1]);
                __stcs((uint32_t*)(Y + (size_t)row * F + q * 64 + lane * 2),
                       *reinterpret_cast<uint32_t*>(&h));
            }
        } else {
            float* Y = (float*)Yv;
            #pragma unroll
            for (int q = 0; q < 4; q++)
                __stcs((float2*)(Y + (size_t)row * F + q * 64 + lane * 2),
                       make_float2(acc[q * 2], acc[q * 2 + 1]));
        }
    }

    if constexpr (STATS) {
        if (valid) {
            #pragma unroll
            for (int q = 0; q < 4; q++) {
                int cb = q * 64 + lane * 2;
                atomicAdd(&ssum[cb], acc[q * 2]);
                atomicAdd(&ssum[cb + 1], acc[q * 2 + 1]);
                atomicAdd(&ssumsq[cb], acc[q * 2] * acc[q * 2]);
                atomicAdd(&ssumsq[cb + 1], acc[q * 2 + 1] * acc[q * 2 + 1]);
            }
        }
        __syncthreads();
        atomicAdd(&g_stats[tid], ssum[tid]);
        atomicAdd(&g_stats[tid + 256], ssumsq[tid]);
    }
}

// ---------------- launch ----------------
extern "C" void kernel_launch(void* const* d_in, const int* in_sizes, int n_in,
                              void* d_out, int out_size) {
    const float* feature = (const float*)d_in[0];
    const int*   rows    = (const int*)d_in[1];
    const int*   cols    = (const int*)d_in[2];
    const float* vals    = (const float*)d_in[3];
    const float* W1      = (const float*)d_in[4];
    const float* W2      = (const float*)d_in[5];
    const float* gamma   = (const float*)d_in[6];
    const float* beta    = (const float*)d_in[7];
    float* out = (float*)d_out;

    int N_ = in_sizes[0] / F;
    int E_ = in_sizes[1];

    __half *p_H16, *p_Xh, *p_Wh;
    int* p_cnt;
    cudaGetSymbolAddress((void**)&p_H16, g_H16);
    cudaGetSymbolAddress((void**)&p_Xh, g_Xh);
    cudaGetSymbolAddress((void**)&p_Wh, g_Wh);
    cudaGetSymbolAddress((void**)&p_cnt, g_cnt);

    const int smem_bytes = 64 * EPLD * sizeof(float) > 2 * STAGE_H * (int)sizeof(__half)
                         ? 64 * EPLD * sizeof(float) : 2 * STAGE_H * (int)sizeof(__half);
    cudaFuncSetAttribute(k_gemm_wmma<0, 0>, cudaFuncAttributeMaxDynamicSharedMemorySize, smem_bytes);
    cudaFuncSetAttribute(k_gemm_wmma<1, 1>, cudaFuncAttributeMaxDynamicSharedMemorySize, smem_bytes);

    static cudaStream_t s2 = nullptr;
    static cudaEvent_t evF = nullptr, evJ = nullptr;
    if (!s2) {
        cudaStreamCreateWithFlags(&s2, cudaStreamNonBlocking);
        cudaEventCreateWithFlags(&evF, cudaEventDisableTiming);
        cudaEventCreateWithFlags(&evJ, cudaEventDisableTiming);
    }

    int gtiles = (N_ + 63) / 64;
    int spmm_blocks = (N_ * 32 + 255) / 256;

    // fork: single-kernel ELL build on s2, hidden under prep_w + GEMM1
    cudaEventRecord(evF, 0);
    cudaStreamWaitEvent(s2, evF, 0);
    cudaMemsetAsync(p_cnt, 0, (size_t)N_ * sizeof(int), s2);

    k_prep_w<<<F * F / 256, 256>>>(W1, W2);                                 // launch 1
    k_gemm_wmma<0, 0><<<gtiles, 256, smem_bytes>>>(feature, p_Wh, p_Xh, N_, gamma, beta); // 2

    k_ell<<<(E_ + 255) / 256, 256, 0, s2>>>(rows, cols, vals, E_);          // 3
    cudaEventRecord(evJ, s2);
    cudaStreamWaitEvent(0, evJ, 0);

    // H16 = (A+I)@support (fp16 out) + fused BN stats
    k_spmm<1, 1><<<spmm_blocks, 256>>>(p_Xh, p_H16, N_);                    // 4 <- ncu capture
    // Xh = relu(BN(H16)) @ W2   (BN finalize folded into prologue)
    k_gemm_wmma<1, 1><<<gtiles, 256, smem_bytes>>>(p_H16, p_Wh + F * F, p_Xh, N_, gamma, beta);
    // out = (A+I)@Xh  (fp32 out)
    k_spmm<0, 0><<<spmm_blocks, 256>>>(p_Xh, out, N_);
}

// round 17
// speedup vs baseline: 1.3348x; 1.0244x over previous
#include <cuda_runtime.h>
#include <cuda_bf16.h>
#include <cuda_fp16.h>
#include <mma.h>
#include <cstdint>
#include <math.h>

using namespace nvcuda;

#define F 256
#define MAXN 100000
#define MAXE 3200000
#define ELLW 128

// ---------------- device scratch ----------------
__device__ __half g_H16[(size_t)MAXN * F];      // SpMM1 output (fp16, read by GEMM2)
__device__ __half g_Xh[(size_t)MAXN * F];       // fp16 copy of current GEMM output
__device__ int   g_cnt[MAXN];                   // per-row edge count (ELL)
__device__ uint2 g_edge[(size_t)MAXN * ELLW];   // ELL: packed (col, val_bits); pad slots stay zero
__device__ float g_stats[2 * F];                // [0:256) sum, [256:512) sumsq
__device__ __half g_Wh[2 * F * F];              // W1, W2 pre-converted to fp16

__device__ __forceinline__ uint32_t smem_u32(const void* p) {
    uint32_t a;
    asm("{ .reg .u64 t; cvta.to.shared.u64 t, %1; cvt.u32.u64 %0, t; }" : "=r"(a) : "l"(p));
    return a;
}

// ---------------- ELL build (single kernel; cnt pre-zeroed by memset) ----------------
__global__ void k_ell(const int* __restrict__ rows, const int* __restrict__ cols,
                      const float* __restrict__ vals, int E) {
    int e = blockIdx.x * blockDim.x + threadIdx.x;
    if (e < E) {
        int r = __ldcs(rows + e);
        int pos = atomicAdd(&g_cnt[r], 1);
        g_edge[(size_t)r * ELLW + pos] = make_uint2((uint32_t)__ldcs(cols + e),
                                                    __float_as_uint(__ldcs(vals + e)));
    }
}

// ---------------- W convert to fp16 (+ zero stats) ----------------
__global__ void k_prep_w(const float* __restrict__ W1, const float* __restrict__ W2) {
    int i = blockIdx.x * blockDim.x + threadIdx.x;
    if (blockIdx.x == 0) { g_stats[threadIdx.x] = 0.f; g_stats[threadIdx.x + 256] = 0.f; }
    g_Wh[i]         = __float2half_rn(W1[i]);
    g_Wh[i + F * F] = __float2half_rn(W2[i]);
}

// ---------------- fp16 wmma GEMM (A: fp32 or fp16), fp16 output ----------------
#define ALD_H 40
#define BLD_H 264
#define ASZ_H (64 * ALD_H)
#define BSZ_H (32 * BLD_H)
#define STAGE_H (ASZ_H + BSZ_H)
#define EPLD 264

__device__ __forceinline__ void cp16(uint32_t dst, const void* src) {
    asm volatile("cp.async.ca.shared.global [%0], [%1], 16;" :: "r"(dst), "l"(src));
}

template <int AHALF, int BNRELU>
__global__ void __launch_bounds__(256)
k_gemm_wmma(const void* __restrict__ Av, const __half* __restrict__ Wh,
            __half* __restrict__ Ch, int M,
            const float* __restrict__ gamma, const float* __restrict__ beta) {
    extern __shared__ float sm[];
    __half* smh = reinterpret_cast<__half*>(sm);
    __shared__ float sa[256], sb[256];
    int tid = threadIdx.x;
    int wid = tid >> 5;
    int warp_row = wid >> 2;
    int warp_col = wid & 3;
    int row0 = blockIdx.x * 64;

    if constexpr (BNRELU) {
        float invM = 1.f / (float)M;
        float m = g_stats[tid] * invM;
        float var = g_stats[tid + 256] * invM - m * m;
        float r = rsqrtf(var + 1e-5f);
        float a = gamma[tid] * r;
        sa[tid] = a;
        sb[tid] = beta[tid] - m * a;
        __syncthreads();
    }

    wmma::fragment<wmma::accumulator, 16, 16, 16, float> acc[2][4];
    #pragma unroll
    for (int i = 0; i < 2; i++)
        #pragma unroll
        for (int j = 0; j < 4; j++) wmma::fill_fragment(acc[i][j], 0.f);

    int a_r0 = AHALF ? (tid >> 2) : (tid >> 3);
    int a_c0 = AHALF ? ((tid & 3) * 8) : ((tid & 7) * 4);

    float areg[8];
    auto load_A = [&](int k0) {
        if constexpr (AHALF) {
            const __half* Ah = (const __half*)Av;
            int gr = row0 + a_r0;
            uint4 u = make_uint4(0, 0, 0, 0);
            if (gr < M) u = *(const uint4*)(Ah + (size_t)gr * F + k0 * 32 + a_c0);
            __half2* hp = reinterpret_cast<__half2*>(&u);
            #pragma unroll
            for (int i = 0; i < 4; i++) {
                float2 p = __half22float2(hp[i]);
                areg[i * 2] = p.x;
                areg[i * 2 + 1] = p.y;
            }
        } else {
            const float* Af = (const float*)Av;
            int gr0 = row0 + a_r0, gr1 = row0 + a_r0 + 32;
            float4 v0 = (gr0 < M) ? *(const float4*)(Af + (size_t)gr0 * F + k0 * 32 + a_c0)
                                  : make_float4(0.f, 0.f, 0.f, 0.f);
            float4 v1 = (gr1 < M) ? *(const float4*)(Af + (size_t)gr1 * F + k0 * 32 + a_c0)
                                  : make_float4(0.f, 0.f, 0.f, 0.f);
            areg[0] = v0.x; areg[1] = v0.y; areg[2] = v0.z; areg[3] = v0.w;
            areg[4] = v1.x; areg[5] = v1.y; areg[6] = v1.z; areg[7] = v1.w;
        }
        if constexpr (BNRELU) {
            int c = k0 * 32 + a_c0;
            if constexpr (AHALF) {
                #pragma unroll
                for (int i = 0; i < 8; i++)
                    areg[i] = fmaxf(fmaf(areg[i], sa[c + i], sb[c + i]), 0.f);
            } else {
                #pragma unroll
                for (int i = 0; i < 4; i++) {
                    float ga = sa[c + i], gb = sb[c + i];
                    areg[i]     = fmaxf(fmaf(areg[i],     ga, gb), 0.f);
                    areg[i + 4] = fmaxf(fmaf(areg[i + 4], ga, gb), 0.f);
                }
            }
        }
    };
    auto sts_A = [&](__half* As) {
        if constexpr (AHALF) {
            __half2 h[4];
            #pragma unroll
            for (int i = 0; i < 4; i++)
                h[i] = __floats2half2_rn(areg[i * 2], areg[i * 2 + 1]);
            *(uint4*)(As + a_r0 * ALD_H + a_c0) = *reinterpret_cast<uint4*>(h);
        } else {
            __half2 h0[2], h1[2];
            h0[0] = __floats2half2_rn(areg[0], areg[1]);
            h0[1] = __floats2half2_rn(areg[2], areg[3]);
            h1[0] = __floats2half2_rn(areg[4], areg[5]);
            h1[1] = __floats2half2_rn(areg[6], areg[7]);
            *(uint2*)(As + a_r0 * ALD_H + a_c0) = *reinterpret_cast<uint2*>(h0);
            *(uint2*)(As + (a_r0 + 32) * ALD_H + a_c0) = *reinterpret_cast<uint2*>(h1);
        }
    };
    auto cpB = [&](__half* Bs, int k0) {
        uint32_t bbase = smem_u32(Bs);
        #pragma unroll
        for (int i = 0; i < 4; i++) {
            int idx = tid + i * 256;
            int r = idx >> 5;
            int c8 = (idx & 31) * 8;
            cp16(bbase + (uint32_t)(r * BLD_H + c8) * 2,
                 Wh + (size_t)(k0 * 32 + r) * F + c8);
        }
    };

    int buf = 0;
    load_A(0);
    sts_A(smh);
    cpB(smh + ASZ_H, 0);
    asm volatile("cp.async.commit_group;" ::: "memory");

    for (int k0 = 0; k0 < 8; k0++) {
        if (k0 < 7) load_A(k0 + 1);
        asm volatile("cp.async.wait_group 0;" ::: "memory");
        __syncthreads();
        __half* As = smh + buf * STAGE_H;
        __half* Bs = As + ASZ_H;
        if (k0 < 7) {
            __half* Asn = smh + (buf ^ 1) * STAGE_H;
            sts_A(Asn);
            cpB(Asn + ASZ_H, k0 + 1);
            asm volatile("cp.async.commit_group;" ::: "memory");
        }
        #pragma unroll
        for (int kk = 0; kk < 2; kk++) {
            wmma::fragment<wmma::matrix_a, 16, 16, 16, __half, wmma::row_major> af[2];
            wmma::fragment<wmma::matrix_b, 16, 16, 16, __half, wmma::row_major> bf[4];
            #pragma unroll
            for (int i = 0; i < 2; i++)
                wmma::load_matrix_sync(af[i], As + (warp_row * 32 + i * 16) * ALD_H + kk * 16, ALD_H);
            #pragma unroll
            for (int j = 0; j < 4; j++)
                wmma::load_matrix_sync(bf[j], Bs + (kk * 16) * BLD_H + warp_col * 64 + j * 16, BLD_H);
            #pragma unroll
            for (int i = 0; i < 2; i++)
                #pragma unroll
                for (int j = 0; j < 4; j++)
                    wmma::mma_sync(acc[i][j], af[i], bf[j], acc[i][j]);
        }
        __syncthreads();
        buf ^= 1;
    }

    // epilogue: frags -> smem(float) -> coalesced fp16 store
    float* ep = sm;
    #pragma unroll
    for (int i = 0; i < 2; i++)
        #pragma unroll
        for (int j = 0; j < 4; j++)
            wmma::store_matrix_sync(ep + (size_t)(warp_row * 32 + i * 16) * EPLD + warp_col * 64 + j * 16,
                                    acc[i][j], EPLD, wmma::mem_row_major);
    __syncthreads();

    #pragma unroll
    for (int it = 0; it < 8; it++) {
        int idx = tid + it * 256;
        int r = idx >> 5;
        int g = idx & 31;
        int grow = row0 + r;
        if (grow < M) {
            float4 v0 = *(float4*)(ep + r * EPLD + g * 8);
            float4 v1 = *(float4*)(ep + r * EPLD + g * 8 + 4);
            __half2 h[4];
            h[0] = __floats2half2_rn(v0.x, v0.y);
            h[1] = __floats2half2_rn(v0.z, v0.w);
            h[2] = __floats2half2_rn(v1.x, v1.y);
            h[3] = __floats2half2_rn(v1.z, v1.w);
            *(uint4*)(Ch + (size_t)grow * F + g * 8) = *reinterpret_cast<uint4*>(h);
        }
    }
}

// ---------------- SpMM: warp/row, padded-deg micro-batches, atomic-free stats ----------------
template <int OUT16, int STATS>
__global__ void __launch_bounds__(256, 6)
k_spmm(const __half* __restrict__ Xh, void* __restrict__ Yv, int Nn) {
    __shared__ float sslice[8][512];   // per-warp: [0:256) sum, [256:512) sumsq (STATS only)
    int tid = threadIdx.x;
    int wid = tid >> 5;
    int lane = tid & 31;
    int row = (blockIdx.x * 256 + tid) >> 5;
    bool valid = (row < Nn);

    float acc[8] = {0.f, 0.f, 0.f, 0.f, 0.f, 0.f, 0.f, 0.f};  // features q*64 + lane*2 + {0,1}
    if (valid) {
        const __half* Xq = Xh + lane * 2;    // + q*64 + row*F
        // self loop: 4 single-wavefront loads
        {
            uint32_t s[4];
            #pragma unroll
            for (int q = 0; q < 4; q++)
                s[q] = __ldg((const uint32_t*)(Xq + (size_t)row * F + q * 64));
            #pragma unroll
            for (int q = 0; q < 4; q++) {
                float2 p = __half22float2(*reinterpret_cast<const __half2*>(&s[q]));
                acc[q * 2] = p.x;
                acc[q * 2 + 1] = p.y;
            }
        }

        // degree padded to multiple of 4; pad slots are never written -> (col=0, val=0)
        int deg = g_cnt[row];
        int degp = (deg + 3) & ~3;
        const uint2* eb = g_edge + (size_t)row * ELLW;
        for (int e = 0; e < degp; e += 32) {
            int m = degp - e;
            if (m > 32) m = 32;
            uint2 ed = __ldg(eb + e + lane);   // unconditional: always in-bounds within ELLW
            for (int j = 0; j < m; j += 4) {
                uint32_t gbuf[4][4];
                #pragma unroll
                for (int k = 0; k < 4; k++) {
                    int cj = __shfl_sync(0xffffffffu, (int)ed.x, j + k);
                    const __half* src = Xq + (size_t)cj * F;
                    #pragma unroll
                    for (int q = 0; q < 4; q++)
                        gbuf[k][q] = __ldg((const uint32_t*)(src + q * 64));
                }
                #pragma unroll
                for (int k = 0; k < 4; k++) {
                    float vj = __uint_as_float(__shfl_sync(0xffffffffu, ed.y, j + k));
                    #pragma unroll
                    for (int q = 0; q < 4; q++) {
                        float2 p = __half22float2(*reinterpret_cast<const __half2*>(&gbuf[k][q]));
                        acc[q * 2]     = fmaf(vj, p.x, acc[q * 2]);
                        acc[q * 2 + 1] = fmaf(vj, p.y, acc[q * 2 + 1]);
                    }
                }
            }
        }
        // store: per quarter, 4B/lane coalesced (fp16) or 8B/lane (fp32)
        if constexpr (OUT16) {
            __half* Y = (__half*)Yv;
            #pragma unroll
            for (int q = 0; q < 4; q++) {
                __half2 h = __floats2half2_rn(acc[q * 2], acc[q * 2 + 1]);
                __stcs((uint32_t*)(Y + (size_t)row * F + q * 64 + lane * 2),
                       *reinterpret_cast<uint32_t*>(&h));
            }
        } else {
            float* Y = (float*)Yv;
            #pragma unroll
            for (int q = 0; q < 4; q++)
                __stcs((float2*)(Y + (size_t)row * F + q * 64 + lane * 2),
                       make_float2(acc[q * 2], acc[q * 2 + 1]));
        }
    }

    if constexpr (STATS) {
        // atomic-free: per-warp slices (invalid rows contribute zeros), tree-reduce, 2 global atomics/thread
        #pragma unroll
        for (int q = 0; q < 4; q++) {
            int cb = q * 64 + lane * 2;
            sslice[wid][cb]           = acc[q * 2];
            sslice[wid][cb + 1]       = acc[q * 2 + 1];
            sslice[wid][256 + cb]     = acc[q * 2] * acc[q * 2];
            sslice[wid][256 + cb + 1] = acc[q * 2 + 1] * acc[q * 2 + 1];
        }
        __syncthreads();
        float s0 = 0.f, s1 = 0.f;
        #pragma unroll
        for (int w = 0; w < 8; w++) {
            s0 += sslice[w][tid];
            s1 += sslice[w][256 + tid];
        }
        atomicAdd(&g_stats[tid], s0);
        atomicAdd(&g_stats[tid + 256], s1);
    }
}

// ---------------- launch ----------------
extern "C" void kernel_launch(void* const* d_in, const int* in_sizes, int n_in,
                              void* d_out, int out_size) {
    const float* feature = (const float*)d_in[0];
    const int*   rows    = (const int*)d_in[1];
    const int*   cols    = (const int*)d_in[2];
    const float* vals    = (const float*)d_in[3];
    const float* W1      = (const float*)d_in[4];
    const float* W2      = (const float*)d_in[5];
    const float* gamma   = (const float*)d_in[6];
    const float* beta    = (const float*)d_in[7];
    float* out = (float*)d_out;

    int N_ = in_sizes[0] / F;
    int E_ = in_sizes[1];

    __half *p_H16, *p_Xh, *p_Wh;
    int* p_cnt;
    cudaGetSymbolAddress((void**)&p_H16, g_H16);
    cudaGetSymbolAddress((void**)&p_Xh, g_Xh);
    cudaGetSymbolAddress((void**)&p_Wh, g_Wh);
    cudaGetSymbolAddress((void**)&p_cnt, g_cnt);

    const int smem_bytes = 64 * EPLD * sizeof(float) > 2 * STAGE_H * (int)sizeof(__half)
                         ? 64 * EPLD * sizeof(float) : 2 * STAGE_H * (int)sizeof(__half);
    cudaFuncSetAttribute(k_gemm_wmma<0, 0>, cudaFuncAttributeMaxDynamicSharedMemorySize, smem_bytes);
    cudaFuncSetAttribute(k_gemm_wmma<1, 1>, cudaFuncAttributeMaxDynamicSharedMemorySize, smem_bytes);

    static cudaStream_t s2 = nullptr;
    static cudaEvent_t evF = nullptr, evJ = nullptr;
    if (!s2) {
        cudaStreamCreateWithFlags(&s2, cudaStreamNonBlocking);
        cudaEventCreateWithFlags(&evF, cudaEventDisableTiming);
        cudaEventCreateWithFlags(&evJ, cudaEventDisableTiming);
    }

    int gtiles = (N_ + 63) / 64;
    int spmm_blocks = (N_ * 32 + 255) / 256;

    // fork: single-kernel ELL build on s2, hidden under prep_w + GEMM1
    cudaEventRecord(evF, 0);
    cudaStreamWaitEvent(s2, evF, 0);
    cudaMemsetAsync(p_cnt, 0, (size_t)N_ * sizeof(int), s2);

    k_prep_w<<<F * F / 256, 256>>>(W1, W2);                                 // launch 1
    k_gemm_wmma<0, 0><<<gtiles, 256, smem_bytes>>>(feature, p_Wh, p_Xh, N_, gamma, beta); // 2

    k_ell<<<(E_ + 255) / 256, 256, 0, s2>>>(rows, cols, vals, E_);          // 3
    cudaEventRecord(evJ, s2);
    cudaStreamWaitEvent(0, evJ, 0);

    // H16 = (A+I)@support (fp16 out) + fused BN stats
    k_spmm<1, 1><<<spmm_blocks, 256>>>(p_Xh, p_H16, N_);                    // 4 <- ncu capture
    // Xh = relu(BN(H16)) @ W2   (BN finalize folded into prologue)
    k_gemm_wmma<1, 1><<<gtiles, 256, smem_bytes>>>(p_H16, p_Wh + F * F, p_Xh, N_, gamma, beta);
    // out = (A+I)@Xh  (fp32 out)
    k_spmm<0, 0><<<spmm_blocks, 256>>>(p_Xh, out, N_);
}